// round 10
// baseline (speedup 1.0000x reference)
#include <cuda_runtime.h>
#include <math.h>

#define NR 4096
#define MAXS 128
typedef unsigned long long ull;

// ---------------- scratch (device globals) ----------------
__device__ float g_z0[NR * MAXS], g_z1[NR * MAXS];   // z ping-pong, layout [s][r]
__device__ float g_s0[NR * MAXS], g_s1[NR * MAXS];   // sdf ping-pong
__device__ float g_newz[NR * 16], g_newsdf[NR * 16]; // [t][r]
__device__ float g_w[NR * MAXS];                     // upsample weights scratch
__device__ float g_fsdf[NR * MAXS], g_tc[NR * MAXS]; // final pass, [s][r]
__device__ float g_g2[NR * MAXS * 128];              // g2 per final point, [tile][p][j]

// ---------------- helpers ----------------
__device__ __forceinline__ ull pack2(float lo, float hi) {
    ull d; asm("mov.b64 %0, {%1, %2};" : "=l"(d) : "f"(lo), "f"(hi)); return d;
}
__device__ __forceinline__ void unpack2(ull v, float& lo, float& hi) {
    asm("mov.b64 {%0, %1}, %2;" : "=f"(lo), "=f"(hi) : "l"(v));
}
__device__ __forceinline__ ull ffma2(ull a, ull b, ull c) {
    ull d; asm("fma.rn.f32x2 %0, %1, %2, %3;" : "=l"(d) : "l"(a), "l"(b), "l"(c)); return d;
}
__device__ __forceinline__ ull fadd2(ull a, ull b) {
    ull d; asm("add.rn.f32x2 %0, %1, %2;" : "=l"(d) : "l"(a), "l"(b)); return d;
}
__device__ __forceinline__ float softplusf(float x) {
    return fmaxf(x, 0.f) + log1pf(expf(-fabsf(x)));
}
__device__ __forceinline__ float sigmoidf(float x) {
    return 1.f / (1.f + expf(-x));
}

// ---------------- init z (linspace, [s][r]) ----------------
__global__ void k_init_z(const float* __restrict__ near_, const float* __restrict__ far_) {
    int idx = blockIdx.x * blockDim.x + threadIdx.x;
    if (idx >= NR * 64) return;
    int r = idx & (NR - 1), s = idx >> 12;
    float t = (s == 63) ? 1.0f : s * (1.0f / 63.0f);
    g_z0[s * NR + r] = near_[r] + (far_[r] - near_[r]) * t;
}

// =====================================================================
// GEMM-structured MLP kernels, 2 blocks/SM, j-packed accumulators.
// Block = 256 threads = 128-point tile. Thread (tp=t>>4, tj=t&15):
// 8 points (scalar) x 4 j-pairs (j = 2tj+32q, 2tj+1+32q).
// Staging buffers store values DUPLICATED (h,h) so splats load directly.
// =====================================================================

#define SDUP 260   // duplicated staging row stride in floats (16B-aligned, 4-way worst)

// fwd smem floats: W2s 16384 | ATd 32*260 | W1s 384 | b1s/b2s/W3s | xs/ys/zs
#define SMEM_F   (25856 * 4)
// bwd smem floats: W2Ts 128*132 | G2d 32*260 | W1s 384 | b1s | xs/ys/zs/dxs/dys/dzs
#define SMEM_BWD (26496 * 4)

// stage 1 chunk: h1 (duplicated) for i in [32c, 32c+32) -> ATd[il][2p]
__device__ __forceinline__ void stage1_chunk(
    int c, int t, float* ATd, const float* W1s, const float* b1s,
    const float* xs, const float* ys, const float* zs)
{
    int p = t & 127, ih = t >> 7;
    float xv = xs[p], yv = ys[p], zv = zs[p];
    #pragma unroll
    for (int il = 16 * ih; il < 16 * ih + 16; il++) {
        int i = 32 * c + il;
        float a = fmaf(xv, W1s[i], fmaf(yv, W1s[128 + i], fmaf(zv, W1s[256 + i], b1s[i])));
        float h = softplusf(a);
        *(ull*)(ATd + il * SDUP + 2 * p) = pack2(h, h);
    }
}

// GEMM chunk (fwd): acc[k][q] += splat(h1[p]) * (W2[i][2jj], W2[i][2jj+1])
__device__ __forceinline__ void gemm_chunk_f(
    int c, int tp, int tj, const float* ATd, const float* W2s, ull acc[8][4])
{
    #pragma unroll 2
    for (int il = 0; il < 32; il++) {
        int i = 32 * c + il;
        const float* arow = ATd + il * SDUP + 16 * tp;
        ulonglong2 A0 = *(const ulonglong2*)(arow);
        ulonglong2 A1 = *(const ulonglong2*)(arow + 4);
        ulonglong2 A2 = *(const ulonglong2*)(arow + 8);
        ulonglong2 A3 = *(const ulonglong2*)(arow + 12);
        const float* wrow = W2s + i * 128 + 2 * tj;
        ull w0 = *(const ull*)(wrow);
        ull w1 = *(const ull*)(wrow + 32);
        ull w2 = *(const ull*)(wrow + 64);
        ull w3 = *(const ull*)(wrow + 96);
        ull sp[8] = {A0.x, A0.y, A1.x, A1.y, A2.x, A2.y, A3.x, A3.y};
        #pragma unroll
        for (int k = 0; k < 8; k++) {
            acc[k][0] = ffma2(sp[k], w0, acc[k][0]);
            acc[k][1] = ffma2(sp[k], w1, acc[k][1]);
            acc[k][2] = ffma2(sp[k], w2, acc[k][2]);
            acc[k][3] = ffma2(sp[k], w3, acc[k][3]);
        }
    }
}

template <bool WG2>
__device__ __forceinline__ void mlp_fwd_body(
    const float* __restrict__ W1, const float* __restrict__ b1,
    const float* __restrict__ W2, const float* __restrict__ b2,
    const float* __restrict__ W3, const float* __restrict__ b3,
    const float* __restrict__ ro, const float* __restrict__ rd,
    float* sm, float* outb, float* g2out_base, int mode)
{
    float* W2s = sm;
    float* ATd = sm + 16384;
    float* W1s = sm + 24704;
    float* b1s = sm + 25088;
    float* b2s = sm + 25216;
    float* W3s = sm + 25344;
    float* xs  = sm + 25472;
    float* ys  = sm + 25600;
    float* zs  = sm + 25728;
    int t = threadIdx.x;

    for (int e = t; e < 16384; e += 256) W2s[e] = W2[e];
    for (int e = t; e < 384; e += 256) W1s[e] = W1[e];
    if (t < 128) { b1s[t] = b1[t]; b2s[t] = b2[t]; W3s[t] = W3[t]; }
    if (t < 128) {
        int gidx = blockIdx.x * 128 + t;
        int r = gidx & (NR - 1);
        float z;
        if (WG2) {
            int s = gidx >> 12;
            float zk = g_z0[gidx];
            float dist = (s < 127) ? (g_z0[gidx + NR] - zk) : 0.03125f;  // SAMPLE_DIST
            z = zk + 0.5f * dist;
        } else {
            z = (mode == 0) ? g_z0[gidx] : g_newz[gidx];
        }
        xs[t] = ro[3*r]   + rd[3*r]   * z;
        ys[t] = ro[3*r+1] + rd[3*r+1] * z;
        zs[t] = ro[3*r+2] + rd[3*r+2] * z;
    }
    __syncthreads();

    int tp = t >> 4, tj = t & 15;
    ull acc[8][4];
    #pragma unroll
    for (int k = 0; k < 8; k++)
        #pragma unroll
        for (int q = 0; q < 4; q++) acc[k][q] = 0;

    #pragma unroll 1
    for (int c = 0; c < 4; c++) {
        if (c) __syncthreads();
        stage1_chunk(c, t, ATd, W1s, b1s, xs, ys, zs);
        __syncthreads();
        gemm_chunk_f(c, tp, tj, ATd, W2s, acc);
    }

    // epilogue: sdf = b3 + sum_j softplus(a2+b2)*W3 ; optional g2 = sig*W3 store
    float* g2out = WG2 ? (g2out_base + (size_t)blockIdx.x * 16384) : nullptr;
    ull sdfp[8] = {0,0,0,0,0,0,0,0};
    #pragma unroll
    for (int q = 0; q < 4; q++) {
        ull b2p = *(const ull*)(b2s + 2*tj + 32*q);
        ull w3p = *(const ull*)(W3s + 2*tj + 32*q);
        float w3lo, w3hi; unpack2(w3p, w3lo, w3hi);
        #pragma unroll
        for (int k = 0; k < 8; k++) {
            ull a = fadd2(acc[k][q], b2p);
            float alo, ahi; unpack2(a, alo, ahi);
            if (WG2) {
                float elo = expf(-fabsf(alo)), ehi = expf(-fabsf(ahi));
                float h2lo = fmaxf(alo, 0.f) + log1pf(elo);
                float h2hi = fmaxf(ahi, 0.f) + log1pf(ehi);
                sdfp[k] = ffma2(pack2(h2lo, h2hi), w3p, sdfp[k]);
                float siglo = (alo >= 0.f) ? (1.f / (1.f + elo)) : (elo / (1.f + elo));
                float sighi = (ahi >= 0.f) ? (1.f / (1.f + ehi)) : (ehi / (1.f + ehi));
                *(ull*)(g2out + (8*tp + k) * 128 + 2*tj + 32*q) = pack2(siglo * w3lo, sighi * w3hi);
            } else {
                sdfp[k] = ffma2(pack2(softplusf(alo), softplusf(ahi)), w3p, sdfp[k]);
            }
        }
    }
    #pragma unroll
    for (int m = 1; m < 16; m <<= 1)
        #pragma unroll
        for (int k = 0; k < 8; k++)
            sdfp[k] = fadd2(sdfp[k], __shfl_xor_sync(0xffffffffu, sdfp[k], m, 16));
    if (tj == 0) {
        float b3v = b3[0];
        int gb = blockIdx.x * 128 + 8*tp;
        #pragma unroll
        for (int k = 0; k < 8; k++) {
            float lo, hi; unpack2(sdfp[k], lo, hi);
            outb[gb + k] = (lo + hi) + b3v;
        }
    }
}

__global__ __launch_bounds__(256, 2) void k_mlp_fwd(
    const float* __restrict__ W1, const float* __restrict__ b1,
    const float* __restrict__ W2, const float* __restrict__ b2,
    const float* __restrict__ W3, const float* __restrict__ b3,
    const float* __restrict__ ro, const float* __restrict__ rd, int mode)
{
    extern __shared__ float sm[];
    mlp_fwd_body<false>(W1, b1, W2, b2, W3, b3, ro, rd, sm,
                        (mode == 0) ? g_s0 : g_newsdf, nullptr, mode);
}

__global__ __launch_bounds__(256, 2) void k_mlp_fwd_g2(
    const float* __restrict__ W1, const float* __restrict__ b1,
    const float* __restrict__ W2, const float* __restrict__ b2,
    const float* __restrict__ W3, const float* __restrict__ b3,
    const float* __restrict__ ro, const float* __restrict__ rd)
{
    extern __shared__ float sm[];
    mlp_fwd_body<true>(W1, b1, W2, b2, W3, b3, ro, rd, sm, g_fsdf, g_g2, 0);
}

// backward: g1 = g2 @ W2^T (i-packed pairs), grad = W1 @ (sigmoid(a1)*g1)
__global__ __launch_bounds__(256, 2) void k_mlp_bwd(
    const float* __restrict__ W1, const float* __restrict__ b1,
    const float* __restrict__ W2,
    const float* __restrict__ ro, const float* __restrict__ rd,
    float* __restrict__ grad_out)
{
    extern __shared__ float sm[];
    float* W2Ts = sm;              // [j][i], stride 132 (natural i-pairs)
    float* G2d  = sm + 16896;      // duplicated chunk [jl][2p], stride SDUP
    float* W1s  = sm + 25216;
    float* b1s  = sm + 25600;
    float* xs   = sm + 25728;
    float* ys   = sm + 25856;
    float* zs   = sm + 25984;
    float* dxs  = sm + 26112;
    float* dys  = sm + 26240;
    float* dzs  = sm + 26368;
    int t = threadIdx.x;

    for (int e = t; e < 16384; e += 256) W2Ts[(e & 127) * 132 + (e >> 7)] = W2[e];
    for (int e = t; e < 384; e += 256) W1s[e] = W1[e];
    if (t < 128) b1s[t] = b1[t];
    if (t < 128) {
        int gidx = blockIdx.x * 128 + t;
        int r = gidx & (NR - 1), s = gidx >> 12;
        float zk = g_z0[gidx];
        float dist = (s < 127) ? (g_z0[gidx + NR] - zk) : 0.03125f;
        float midz = zk + 0.5f * dist;
        float dx = rd[3*r], dy = rd[3*r+1], dz = rd[3*r+2];
        dxs[t] = dx; dys[t] = dy; dzs[t] = dz;
        xs[t] = ro[3*r]   + dx * midz;
        ys[t] = ro[3*r+1] + dy * midz;
        zs[t] = ro[3*r+2] + dz * midz;
    }

    int tp = t >> 4, ti = t & 15;
    const float* g2in = g_g2 + (size_t)blockIdx.x * 16384;
    ull acc2[8][4];
    #pragma unroll
    for (int k = 0; k < 8; k++)
        #pragma unroll
        for (int u = 0; u < 4; u++) acc2[k][u] = 0;

    #pragma unroll 1
    for (int c = 0; c < 4; c++) {
        __syncthreads();   // covers init loads (c=0) / previous chunk readers done
        // stage g2 chunk duplicated: G2d[jl][2p] = (g2[p][32c+jl], same)
        for (int e = t; e < 4096; e += 256) {
            int p = e >> 5, jl = e & 31;
            float v = g2in[p * 128 + 32 * c + jl];
            *(ull*)(G2d + jl * SDUP + 2 * p) = pack2(v, v);
        }
        __syncthreads();
        #pragma unroll 2
        for (int jl = 0; jl < 32; jl++) {
            int j = 32 * c + jl;
            const float* grow = G2d + jl * SDUP + 16 * tp;
            ulonglong2 A0 = *(const ulonglong2*)(grow);
            ulonglong2 A1 = *(const ulonglong2*)(grow + 4);
            ulonglong2 A2 = *(const ulonglong2*)(grow + 8);
            ulonglong2 A3 = *(const ulonglong2*)(grow + 12);
            const float* wrow = W2Ts + j * 132 + 2 * ti;
            ull w0 = *(const ull*)(wrow);
            ull w1 = *(const ull*)(wrow + 32);
            ull w2 = *(const ull*)(wrow + 64);
            ull w3 = *(const ull*)(wrow + 96);
            ull sp[8] = {A0.x, A0.y, A1.x, A1.y, A2.x, A2.y, A3.x, A3.y};
            #pragma unroll
            for (int k = 0; k < 8; k++) {
                acc2[k][0] = ffma2(sp[k], w0, acc2[k][0]);
                acc2[k][1] = ffma2(sp[k], w1, acc2[k][1]);
                acc2[k][2] = ffma2(sp[k], w2, acc2[k][2]);
                acc2[k][3] = ffma2(sp[k], w3, acc2[k][3]);
            }
        }
    }

    // epilogue: per point, grad = sum_i W1[:,i] * sigmoid(a1_i) * g1_i  (i-pairs)
    int gb = blockIdx.x * 128;
    int s = gb >> 12;
    int rb = gb & (NR - 1);
    #pragma unroll 1
    for (int k = 0; k < 8; k++) {
        int p = 8 * tp + k;
        float xv = xs[p], yv = ys[p], zv = zs[p];
        ull xsp = pack2(xv, xv), ysp = pack2(yv, yv), zsp = pack2(zv, zv);
        ull gxp = 0, gyp = 0, gzp = 0;
        #pragma unroll
        for (int u = 0; u < 4; u++) {
            int ib = 2 * ti + 32 * u;
            ull w1x = *(const ull*)(W1s + ib);
            ull w1y = *(const ull*)(W1s + 128 + ib);
            ull w1z = *(const ull*)(W1s + 256 + ib);
            ull b1p = *(const ull*)(b1s + ib);
            ull a1 = ffma2(xsp, w1x, ffma2(ysp, w1y, ffma2(zsp, w1z, b1p)));
            float alo, ahi; unpack2(a1, alo, ahi);
            float glo, ghi; unpack2(acc2[k][u], glo, ghi);
            ull gi = pack2(glo * sigmoidf(alo), ghi * sigmoidf(ahi));
            gxp = ffma2(w1x, gi, gxp);
            gyp = ffma2(w1y, gi, gyp);
            gzp = ffma2(w1z, gi, gzp);
        }
        #pragma unroll
        for (int m = 1; m < 16; m <<= 1) {
            gxp = fadd2(gxp, __shfl_xor_sync(0xffffffffu, gxp, m, 16));
            gyp = fadd2(gyp, __shfl_xor_sync(0xffffffffu, gyp, m, 16));
            gzp = fadd2(gzp, __shfl_xor_sync(0xffffffffu, gzp, m, 16));
        }
        if (ti == 0) {
            float l0, h0, l1, h1, l2, h2;
            unpack2(gxp, l0, h0); unpack2(gyp, l1, h1); unpack2(gzp, l2, h2);
            float gx = l0 + h0, gy = l1 + h1, gz = l2 + h2;
            int o = 3 * ((rb + p) * 128 + s);
            grad_out[o] = gx; grad_out[o+1] = gy; grad_out[o+2] = gz;
            g_tc[gb + p] = gx * dxs[p] + gy * dys[p] + gz * dzs[p];
        }
    }
}

// ---------------- per-ray upsample + sample_pdf ----------------
__global__ void k_upsample(int S, float inv_s, int flag,
                           const float* __restrict__ ro, const float* __restrict__ rd) {
    int r = blockIdx.x * blockDim.x + threadIdx.x;
    if (r >= NR) return;
    const float* zb = flag ? g_z1 : g_z0;
    const float* fb = flag ? g_s1 : g_s0;
    float ox = ro[3 * r], oy = ro[3 * r + 1], oz = ro[3 * r + 2];
    float dx = rd[3 * r], dy = rd[3 * r + 1], dz = rd[3 * r + 2];

    float T = 1.f, wsum = 0.f, cprev = 0.f;
    float z0v = zb[r], f0 = fb[r];
    float px = ox + dx * z0v, py = oy + dy * z0v, pz = oz + dz * z0v;
    float rad_prev = sqrtf(px * px + py * py + pz * pz);
    for (int k = 0; k < S - 1; k++) {
        float z1v = zb[(k + 1) * NR + r], f1 = fb[(k + 1) * NR + r];
        float qx = ox + dx * z1v, qy = oy + dy * z1v, qz = oz + dz * z1v;
        float rad_next = sqrtf(qx * qx + qy * qy + qz * qz);
        float inside = (rad_prev < 1.f || rad_next < 1.f) ? 1.f : 0.f;
        rad_prev = rad_next;
        float c = (f1 - f0) / (z1v - z0v + 1e-5f);
        float cc = fminf((k == 0) ? 0.f : cprev, c);
        cprev = c;
        cc = fminf(fmaxf(cc, -1000.f), 0.f) * inside;
        float midv = 0.5f * (f0 + f1);
        float dd = z1v - z0v;
        float pc = sigmoidf((midv - cc * dd * 0.5f) * inv_s);
        float nc = sigmoidf((midv + cc * dd * 0.5f) * inv_s);
        float a = (pc - nc + 1e-5f) / (pc + 1e-5f);
        float wk = a * T + 1e-5f;
        T *= (1.f - a + 1e-7f);
        g_w[k * NR + r] = wk;
        wsum += wk;
        z0v = z1v; f0 = f1;
    }

    int t = 0;
    float cb = 0.f, run = 0.f;
    z0v = zb[r];
    for (int k = 0; k < S - 1 && t < 16; k++) {
        float z1v = zb[(k + 1) * NR + r];
        run += g_w[k * NR + r] / wsum;
        while (t < 16) {
            float u = (float)(2 * t + 1) * 0.03125f;
            if (!(u < run)) break;
            float denom = run - cb;
            if (denom < 1e-5f) denom = 1.f;
            float tt = (u - cb) / denom;
            g_newz[t * NR + r] = z0v + tt * (z1v - z0v);
            t++;
        }
        cb = run; z0v = z1v;
    }
    float zlast = zb[(S - 1) * NR + r];
    while (t < 16) { g_newz[t * NR + r] = zlast; t++; }
}

// ---------------- per-ray stable merge (streaming, ping-pong) ----------------
__global__ void k_merge(int S, int flag, int last) {
    int r = blockIdx.x * blockDim.x + threadIdx.x;
    if (r >= NR) return;
    const float* zi = flag ? g_z1 : g_z0;
    float* zo = flag ? g_z0 : g_z1;
    const float* si = flag ? g_s1 : g_s0;
    float* so = flag ? g_s0 : g_s1;
    int i = 0, j = 0;
    float zv = zi[r], nv = g_newz[r];
    for (int t = 0; t < S + 16; t++) {
        bool takeold = (j >= 16) || (i < S && zv <= nv);
        if (takeold) {
            zo[t * NR + r] = zv;
            if (!last) so[t * NR + r] = si[i * NR + r];
            i++;
            if (i < S) zv = zi[i * NR + r];
        } else {
            zo[t * NR + r] = nv;
            if (!last) so[t * NR + r] = g_newsdf[j * NR + r];
            j++;
            if (j < 16) nv = g_newz[j * NR + r];
        }
    }
}

// ---------------- per-ray render (depth) ----------------
__global__ void k_render(const float* __restrict__ variance, float* __restrict__ out) {
    int r = blockIdx.x * blockDim.x + threadIdx.x;
    if (r >= NR) return;
    float inv_s = expf(10.f * variance[0]);
    inv_s = fminf(fmaxf(inv_s, 1e-6f), 1e6f);
    float T = 1.f, depth = 0.f;
    for (int k = 0; k < 128; k++) {
        float zk = g_z0[k * NR + r];
        float dist = (k < 127) ? (g_z0[(k + 1) * NR + r] - zk) : 0.03125f;
        float tc = g_tc[k * NR + r];
        float itc = -fmaxf(0.5f - 0.5f * tc, 0.f);   // COS_ANNEAL_RATIO = 0
        float sdf = g_fsdf[k * NR + r];
        float pc = sigmoidf((sdf - itc * dist * 0.5f) * inv_s);
        float nc = sigmoidf((sdf + itc * dist * 0.5f) * inv_s);
        float a = (pc - nc + 1e-5f) / (pc + 1e-5f);
        a = fminf(fmaxf(a, 0.f), 1.f);
        depth += a * T * zk;
        T *= (1.f - a + 1e-7f);
    }
    out[r] = depth;
}

// ---------------- launch ----------------
extern "C" void kernel_launch(void* const* d_in, const int* in_sizes, int n_in,
                              void* d_out, int out_size) {
    const float* rays_o = (const float*)d_in[0];
    const float* rays_d = (const float*)d_in[1];
    const float* near_  = (const float*)d_in[2];
    const float* far_   = (const float*)d_in[3];
    const float* W1 = (const float*)d_in[4];
    const float* b1 = (const float*)d_in[5];
    const float* W2 = (const float*)d_in[6];
    const float* b2 = (const float*)d_in[7];
    const float* W3 = (const float*)d_in[8];
    const float* b3 = (const float*)d_in[9];
    const float* var = (const float*)d_in[10];
    float* out = (float*)d_out;

    cudaFuncSetAttribute(k_mlp_fwd,    cudaFuncAttributeMaxDynamicSharedMemorySize, SMEM_F);
    cudaFuncSetAttribute(k_mlp_fwd_g2, cudaFuncAttributeMaxDynamicSharedMemorySize, SMEM_F);
    cudaFuncSetAttribute(k_mlp_bwd,    cudaFuncAttributeMaxDynamicSharedMemorySize, SMEM_BWD);

    // initial coarse sampling: S=64 (262144 points -> 2048 tiles)
    k_init_z<<<(NR * 64) / 256, 256>>>(near_, far_);
    k_mlp_fwd<<<(NR * 64) / 128, 256, SMEM_F>>>(W1, b1, W2, b2, W3, b3, rays_o, rays_d, 0);

    // 4 upsample rounds, +16 samples each; z/sdf ping-pong
    for (int i = 0; i < 4; i++) {
        int S = 64 + 16 * i;
        float inv_s = (float)(64 << i);
        int flag = i & 1;
        k_upsample<<<NR / 32, 32>>>(S, inv_s, flag, rays_o, rays_d);
        if (i < 3)
            k_mlp_fwd<<<(NR * 16) / 128, 256, SMEM_F>>>(W1, b1, W2, b2, W3, b3, rays_o, rays_d, 1);
        k_merge<<<NR / 32, 32>>>(S, flag, (i == 3) ? 1 : 0);
    }

    // final: S=128 (524288 points -> 4096 tiles): fwd(+g2), bwd, render
    k_mlp_fwd_g2<<<(NR * 128) / 128, 256, SMEM_F>>>(W1, b1, W2, b2, W3, b3, rays_o, rays_d);
    k_mlp_bwd<<<(NR * 128) / 128, 256, SMEM_BWD>>>(W1, b1, W2, rays_o, rays_d, out + NR);
    k_render<<<NR / 32, 32>>>(var, out);
}

// round 12
// speedup vs baseline: 1.0506x; 1.0506x over previous
#include <cuda_runtime.h>
#include <math.h>

#define NR 4096
#define MAXS 128
typedef unsigned long long ull;

// ---------------- scratch (device globals) ----------------
__device__ float g_z0[NR * MAXS], g_z1[NR * MAXS];   // z ping-pong, layout [s][r]
__device__ float g_s0[NR * MAXS], g_s1[NR * MAXS];   // sdf ping-pong
__device__ float g_newz[NR * 16], g_newsdf[NR * 16]; // [t][r]
__device__ float g_w[NR * MAXS];                     // upsample weights scratch
__device__ float g_fsdf[NR * MAXS], g_tc[NR * MAXS]; // final pass, [s][r]
__device__ float g_g2[NR * MAXS * 128];              // g2 per final point, [tile][p][j]

// ---------------- helpers ----------------
__device__ __forceinline__ ull pack2(float lo, float hi) {
    ull d; asm("mov.b64 %0, {%1, %2};" : "=l"(d) : "f"(lo), "f"(hi)); return d;
}
__device__ __forceinline__ void unpack2(ull v, float& lo, float& hi) {
    asm("mov.b64 {%0, %1}, %2;" : "=f"(lo), "=f"(hi) : "l"(v));
}
__device__ __forceinline__ ull ffma2(ull a, ull b, ull c) {
    ull d; asm("fma.rn.f32x2 %0, %1, %2, %3;" : "=l"(d) : "l"(a), "l"(b), "l"(c)); return d;
}
__device__ __forceinline__ ull fadd2(ull a, ull b) {
    ull d; asm("add.rn.f32x2 %0, %1, %2;" : "=l"(d) : "l"(a), "l"(b)); return d;
}
__device__ __forceinline__ float softplusf(float x) {
    return fmaxf(x, 0.f) + log1pf(expf(-fabsf(x)));
}
__device__ __forceinline__ float sigmoidf(float x) {
    return 1.f / (1.f + expf(-x));
}

// ---------------- init z (linspace, [s][r]) ----------------
__global__ void k_init_z(const float* __restrict__ near_, const float* __restrict__ far_) {
    int idx = blockIdx.x * blockDim.x + threadIdx.x;
    if (idx >= NR * 64) return;
    int r = idx & (NR - 1), s = idx >> 12;
    float t = (s == 63) ? 1.0f : s * (1.0f / 63.0f);
    g_z0[s * NR + r] = near_[r] + (far_[r] - near_[r]) * t;
}

// =====================================================================
// GEMM-structured MLP kernels (R8 structure), 2 blocks/SM,
// software-pipelined inner loops (prefetch il+1 operands during il FMAs).
// Block = 256 threads = 128-point tile. Thread (tp=t>>4, tj=t&15):
// 8 points (4 f32x2 pairs) x 8 outputs (j = tj+16q).
// h1 staged in a 64-row chunk buffer (i-chunked) to fit 2 blocks/SM.
// =====================================================================

// fwd smem floats: W2s 16384 | ATc 64*132 | W1s 384 | b1s/b2s/W3s 3*128 | xs/ys/zs 3*128
#define SMEM_F   (25984 * 4)
// bwd smem floats: W2Ts 128*132 | G2c 64*132 | W1s 384 | b1s 128 | xs/ys/zs/dxs/dys/dzs 6*128
#define SMEM_BWD (26624 * 4)

// stage 1 chunk: h1 for i in [64c, 64c+64) -> ATc[i_loc][p], conflict-free
__device__ __forceinline__ void stage1_chunk(
    int c, int t, float* ATc, const float* W1s, const float* b1s,
    const float* xs, const float* ys, const float* zs)
{
    int p = t & 127, ih = t >> 7;
    float xv = xs[p], yv = ys[p], zv = zs[p];
    #pragma unroll 4
    for (int il = 32 * ih; il < 32 * ih + 32; il++) {
        int i = 64 * c + il;
        float a = fmaf(xv, W1s[i], fmaf(yv, W1s[128 + i], fmaf(zv, W1s[256 + i], b1s[i])));
        ATc[il * 132 + p] = softplusf(a);
    }
}

// GEMM chunk, software-pipelined:
// acc[p][j] += sum_{i in chunk} h1[p][i] * W2[i][j]
// NOTE: the il+1 prefetch on the last iteration reads one row past ATc / the
// W2 chunk; both land in adjacent ALLOCATED smem regions and the values are
// loaded but never used. Harmless by construction.
__device__ __forceinline__ void gemm_chunk(
    int c, int tp, int tj, const float* ATc, const float* W2s, ull acc[4][8])
{
    const ulonglong2* ATv = (const ulonglong2*)ATc;
    const float* wbase = W2s + (64 * c) * 128 + tj;
    ulonglong2 a01 = ATv[2 * tp];
    ulonglong2 a23 = ATv[2 * tp + 1];
    float wf[8];
    #pragma unroll
    for (int q = 0; q < 8; q++) wf[q] = wbase[16 * q];

    #pragma unroll 2
    for (int il = 0; il < 64; il++) {
        // prefetch next iteration's operands
        ulonglong2 na01 = ATv[(il + 1) * 33 + 2 * tp];
        ulonglong2 na23 = ATv[(il + 1) * 33 + 2 * tp + 1];
        float nwf[8];
        const float* nw = wbase + (il + 1) * 128;
        #pragma unroll
        for (int q = 0; q < 8; q++) nwf[q] = nw[16 * q];
        // FMAs on current operands
        #pragma unroll
        for (int q = 0; q < 8; q++) {
            ull ws = pack2(wf[q], wf[q]);
            acc[0][q] = ffma2(a01.x, ws, acc[0][q]);
            acc[1][q] = ffma2(a01.y, ws, acc[1][q]);
            acc[2][q] = ffma2(a23.x, ws, acc[2][q]);
            acc[3][q] = ffma2(a23.y, ws, acc[3][q]);
        }
        a01 = na01; a23 = na23;
        #pragma unroll
        for (int q = 0; q < 8; q++) wf[q] = nwf[q];
    }
}

__global__ __launch_bounds__(256, 2) void k_mlp_fwd(
    const float* __restrict__ W1, const float* __restrict__ b1,
    const float* __restrict__ W2, const float* __restrict__ b2,
    const float* __restrict__ W3, const float* __restrict__ b3,
    const float* __restrict__ ro, const float* __restrict__ rd,
    int mode)  // 0: z from g_z0 -> g_s0 ; 1: z from g_newz -> g_newsdf
{
    extern __shared__ float sm[];
    float* W2s = sm;
    float* ATc = sm + 16384;
    float* W1s = sm + 24832;
    float* b1s = sm + 25216;
    float* b2s = sm + 25344;
    float* W3s = sm + 25472;
    float* xs  = sm + 25600;
    float* ys  = sm + 25728;
    float* zs  = sm + 25856;
    int t = threadIdx.x;

    for (int e = t; e < 16384; e += 256) W2s[e] = W2[e];
    for (int e = t; e < 384; e += 256) W1s[e] = W1[e];
    if (t < 128) { b1s[t] = b1[t]; b2s[t] = b2[t]; W3s[t] = W3[t]; }
    if (t < 128) {
        int gidx = blockIdx.x * 128 + t;
        int r = gidx & (NR - 1);
        float z = (mode == 0) ? g_z0[gidx] : g_newz[gidx];
        xs[t] = ro[3*r]   + rd[3*r]   * z;
        ys[t] = ro[3*r+1] + rd[3*r+1] * z;
        zs[t] = ro[3*r+2] + rd[3*r+2] * z;
    }
    __syncthreads();

    int tp = t >> 4, tj = t & 15;
    ull acc[4][8];
    #pragma unroll
    for (int pp = 0; pp < 4; pp++)
        #pragma unroll
        for (int q = 0; q < 8; q++) acc[pp][q] = 0;

    #pragma unroll 1
    for (int c = 0; c < 2; c++) {
        if (c) __syncthreads();
        stage1_chunk(c, t, ATc, W1s, b1s, xs, ys, zs);
        __syncthreads();
        gemm_chunk(c, tp, tj, ATc, W2s, acc);
    }

    // epilogue: sdf = b3 + sum_j softplus(a2+b2)*W3
    ull sdfp[4] = {0, 0, 0, 0};
    #pragma unroll
    for (int q = 0; q < 8; q++) {
        int j = tj + 16*q;
        float b2j = b2s[j], w3j = W3s[j];
        ull w3p = pack2(w3j, w3j);
        #pragma unroll
        for (int pp = 0; pp < 4; pp++) {
            float alo, ahi; unpack2(acc[pp][q], alo, ahi);
            alo += b2j; ahi += b2j;
            sdfp[pp] = ffma2(pack2(softplusf(alo), softplusf(ahi)), w3p, sdfp[pp]);
        }
    }
    #pragma unroll
    for (int m = 1; m < 16; m <<= 1)
        #pragma unroll
        for (int pp = 0; pp < 4; pp++)
            sdfp[pp] = fadd2(sdfp[pp], __shfl_xor_sync(0xffffffffu, sdfp[pp], m, 16));
    if (tj == 0) {
        float b3v = b3[0];
        float* outb = (mode == 0) ? g_s0 : g_newsdf;
        int gb = blockIdx.x * 128 + 8*tp;
        #pragma unroll
        for (int pp = 0; pp < 4; pp++) {
            float lo, hi; unpack2(sdfp[pp], lo, hi);
            outb[gb + 2*pp]     = lo + b3v;
            outb[gb + 2*pp + 1] = hi + b3v;
        }
    }
}

// forward for final points (midpoints): writes g_fsdf and g2 -> g_g2 [tile][p][j]
__global__ __launch_bounds__(256, 2) void k_mlp_fwd_g2(
    const float* __restrict__ W1, const float* __restrict__ b1,
    const float* __restrict__ W2, const float* __restrict__ b2,
    const float* __restrict__ W3, const float* __restrict__ b3,
    const float* __restrict__ ro, const float* __restrict__ rd)
{
    extern __shared__ float sm[];
    float* W2s = sm;
    float* ATc = sm + 16384;
    float* W1s = sm + 24832;
    float* b1s = sm + 25216;
    float* b2s = sm + 25344;
    float* W3s = sm + 25472;
    float* xs  = sm + 25600;
    float* ys  = sm + 25728;
    float* zs  = sm + 25856;
    int t = threadIdx.x;

    for (int e = t; e < 16384; e += 256) W2s[e] = W2[e];
    for (int e = t; e < 384; e += 256) W1s[e] = W1[e];
    if (t < 128) { b1s[t] = b1[t]; b2s[t] = b2[t]; W3s[t] = W3[t]; }
    if (t < 128) {
        int gidx = blockIdx.x * 128 + t;
        int r = gidx & (NR - 1), s = gidx >> 12;
        float zk = g_z0[gidx];
        float dist = (s < 127) ? (g_z0[gidx + NR] - zk) : 0.03125f;   // SAMPLE_DIST
        float midz = zk + 0.5f * dist;
        xs[t] = ro[3*r]   + rd[3*r]   * midz;
        ys[t] = ro[3*r+1] + rd[3*r+1] * midz;
        zs[t] = ro[3*r+2] + rd[3*r+2] * midz;
    }
    __syncthreads();

    int tp = t >> 4, tj = t & 15;
    ull acc[4][8];
    #pragma unroll
    for (int pp = 0; pp < 4; pp++)
        #pragma unroll
        for (int q = 0; q < 8; q++) acc[pp][q] = 0;

    #pragma unroll 1
    for (int c = 0; c < 2; c++) {
        if (c) __syncthreads();
        stage1_chunk(c, t, ATc, W1s, b1s, xs, ys, zs);
        __syncthreads();
        gemm_chunk(c, tp, tj, ATc, W2s, acc);
    }

    // epilogue: sdf + g2 store
    float* g2out = g_g2 + (size_t)blockIdx.x * 16384;
    ull sdfp[4] = {0, 0, 0, 0};
    #pragma unroll
    for (int q = 0; q < 8; q++) {
        int j = tj + 16*q;
        float b2j = b2s[j], w3j = W3s[j];
        ull w3p = pack2(w3j, w3j);
        #pragma unroll
        for (int pp = 0; pp < 4; pp++) {
            float alo, ahi; unpack2(acc[pp][q], alo, ahi);
            alo += b2j; ahi += b2j;
            float elo = expf(-fabsf(alo)), ehi = expf(-fabsf(ahi));
            float h2lo = fmaxf(alo, 0.f) + log1pf(elo);
            float h2hi = fmaxf(ahi, 0.f) + log1pf(ehi);
            sdfp[pp] = ffma2(pack2(h2lo, h2hi), w3p, sdfp[pp]);
            float siglo = (alo >= 0.f) ? (1.f / (1.f + elo)) : (elo / (1.f + elo));
            float sighi = (ahi >= 0.f) ? (1.f / (1.f + ehi)) : (ehi / (1.f + ehi));
            int p0 = 8*tp + 2*pp;
            g2out[p0 * 128 + j]       = siglo * w3j;
            g2out[(p0 + 1) * 128 + j] = sighi * w3j;
        }
    }
    #pragma unroll
    for (int m = 1; m < 16; m <<= 1)
        #pragma unroll
        for (int pp = 0; pp < 4; pp++)
            sdfp[pp] = fadd2(sdfp[pp], __shfl_xor_sync(0xffffffffu, sdfp[pp], m, 16));
    if (tj == 0) {
        float b3v = b3[0];
        int gb = blockIdx.x * 128 + 8*tp;
        #pragma unroll
        for (int pp = 0; pp < 4; pp++) {
            float lo, hi; unpack2(sdfp[pp], lo, hi);
            g_fsdf[gb + 2*pp]     = lo + b3v;
            g_fsdf[gb + 2*pp + 1] = hi + b3v;
        }
    }
}

// backward: g1 = g2 @ W2^T, grad = W1 @ (sigmoid(a1)*g1)
__global__ __launch_bounds__(256, 2) void k_mlp_bwd(
    const float* __restrict__ W1, const float* __restrict__ b1,
    const float* __restrict__ W2,
    const float* __restrict__ ro, const float* __restrict__ rd,
    float* __restrict__ grad_out)
{
    extern __shared__ float sm[];
    float* W2Ts = sm;              // [j][i], stride 132
    float* G2c  = sm + 16896;      // 64-row chunk [j_loc][p], stride 132
    float* W1s  = sm + 25344;
    float* b1s  = sm + 25728;
    float* xs   = sm + 25856;
    float* ys   = sm + 25984;
    float* zs   = sm + 26112;
    float* dxs  = sm + 26240;
    float* dys  = sm + 26368;
    float* dzs  = sm + 26496;
    int t = threadIdx.x;

    for (int e = t; e < 16384; e += 256) W2Ts[(e & 127) * 132 + (e >> 7)] = W2[e];
    for (int e = t; e < 384; e += 256) W1s[e] = W1[e];
    if (t < 128) b1s[t] = b1[t];
    if (t < 128) {
        int gidx = blockIdx.x * 128 + t;
        int r = gidx & (NR - 1), s = gidx >> 12;
        float zk = g_z0[gidx];
        float dist = (s < 127) ? (g_z0[gidx + NR] - zk) : 0.03125f;
        float midz = zk + 0.5f * dist;
        float dx = rd[3*r], dy = rd[3*r+1], dz = rd[3*r+2];
        dxs[t] = dx; dys[t] = dy; dzs[t] = dz;
        xs[t] = ro[3*r]   + dx * midz;
        ys[t] = ro[3*r+1] + dy * midz;
        zs[t] = ro[3*r+2] + dz * midz;
    }

    int tp = t >> 4, tj = t & 15, ti = tj;
    const float* g2in = g_g2 + (size_t)blockIdx.x * 16384;
    ull acc2[4][8];
    #pragma unroll
    for (int pp = 0; pp < 4; pp++)
        #pragma unroll
        for (int u = 0; u < 8; u++) acc2[pp][u] = 0;

    #pragma unroll 1
    for (int c = 0; c < 2; c++) {
        __syncthreads();   // covers init loads (c=0) / previous chunk readers done
        for (int e = t; e < 8192; e += 256) {
            int p = e >> 6, jl = e & 63;
            G2c[jl * 132 + p] = g2in[p * 128 + 64 * c + jl];
        }
        __syncthreads();

        // software-pipelined chunk GEMM (overread on last iter lands in
        // adjacent allocated smem and is never used)
        const ulonglong2* G2v = (const ulonglong2*)G2c;
        const float* wbase = W2Ts + (64 * c) * 132 + 2 * 0 + ti;
        ulonglong2 g01 = G2v[2*tp];
        ulonglong2 g23 = G2v[2*tp + 1];
        float wf[8];
        #pragma unroll
        for (int u = 0; u < 8; u++) wf[u] = wbase[16 * u];

        #pragma unroll 2
        for (int jl = 0; jl < 64; jl++) {
            ulonglong2 ng01 = G2v[(jl + 1) * 33 + 2*tp];
            ulonglong2 ng23 = G2v[(jl + 1) * 33 + 2*tp + 1];
            float nwf[8];
            const float* nw = wbase + (jl + 1) * 132;
            #pragma unroll
            for (int u = 0; u < 8; u++) nwf[u] = nw[16 * u];
            #pragma unroll
            for (int u = 0; u < 8; u++) {
                ull ws = pack2(wf[u], wf[u]);
                acc2[0][u] = ffma2(g01.x, ws, acc2[0][u]);
                acc2[1][u] = ffma2(g01.y, ws, acc2[1][u]);
                acc2[2][u] = ffma2(g23.x, ws, acc2[2][u]);
                acc2[3][u] = ffma2(g23.y, ws, acc2[3][u]);
            }
            g01 = ng01; g23 = ng23;
            #pragma unroll
            for (int u = 0; u < 8; u++) wf[u] = nwf[u];
        }
    }

    // epilogue: grad = W1 @ (sigmoid(a1) * g1)
    ull xp[4], yp[4], zp[4];
    {
        const ull* xv = (const ull*)xs; const ull* yv = (const ull*)ys; const ull* zv = (const ull*)zs;
        #pragma unroll
        for (int pp = 0; pp < 4; pp++) { xp[pp] = xv[4*tp+pp]; yp[pp] = yv[4*tp+pp]; zp[pp] = zv[4*tp+pp]; }
    }
    ull gx[4] = {0,0,0,0}, gy[4] = {0,0,0,0}, gz[4] = {0,0,0,0};
    #pragma unroll
    for (int u = 0; u < 8; u++) {
        int ii = ti + 16*u;
        float w1x = W1s[ii], w1y = W1s[128+ii], w1z = W1s[256+ii], b1i = b1s[ii];
        ull wxp = pack2(w1x, w1x), wyp = pack2(w1y, w1y), wzp = pack2(w1z, w1z);
        ull b1p = pack2(b1i, b1i);
        #pragma unroll
        for (int pp = 0; pp < 4; pp++) {
            ull a1 = ffma2(xp[pp], wxp, ffma2(yp[pp], wyp, ffma2(zp[pp], wzp, b1p)));
            float alo, ahi; unpack2(a1, alo, ahi);
            float glo, ghi; unpack2(acc2[pp][u], glo, ghi);
            ull gi = pack2(glo * sigmoidf(alo), ghi * sigmoidf(ahi));
            gx[pp] = ffma2(wxp, gi, gx[pp]);
            gy[pp] = ffma2(wyp, gi, gy[pp]);
            gz[pp] = ffma2(wzp, gi, gz[pp]);
        }
    }
    #pragma unroll
    for (int m = 1; m < 16; m <<= 1)
        #pragma unroll
        for (int pp = 0; pp < 4; pp++) {
            gx[pp] = fadd2(gx[pp], __shfl_xor_sync(0xffffffffu, gx[pp], m, 16));
            gy[pp] = fadd2(gy[pp], __shfl_xor_sync(0xffffffffu, gy[pp], m, 16));
            gz[pp] = fadd2(gz[pp], __shfl_xor_sync(0xffffffffu, gz[pp], m, 16));
        }
    if (ti == 0) {
        int gb = blockIdx.x * 128;
        int s = gb >> 12;
        int rb = (gb & (NR - 1));
        #pragma unroll
        for (int pp = 0; pp < 4; pp++) {
            float gxl, gxh, gyl, gyh, gzl, gzh;
            unpack2(gx[pp], gxl, gxh); unpack2(gy[pp], gyl, gyh); unpack2(gz[pp], gzl, gzh);
            int p0 = 8*tp + 2*pp;
            int o0 = 3 * ((rb + p0) * 128 + s);
            grad_out[o0]   = gxl; grad_out[o0+1] = gyl; grad_out[o0+2] = gzl;
            g_tc[gb + p0] = gxl*dxs[p0] + gyl*dys[p0] + gzl*dzs[p0];
            int o1 = 3 * ((rb + p0 + 1) * 128 + s);
            grad_out[o1]   = gxh; grad_out[o1+1] = gyh; grad_out[o1+2] = gzh;
            g_tc[gb + p0 + 1] = gxh*dxs[p0+1] + gyh*dys[p0+1] + gzh*dzs[p0+1];
        }
    }
}

// ---------------- per-ray upsample + sample_pdf ----------------
__global__ void k_upsample(int S, float inv_s, int flag,
                           const float* __restrict__ ro, const float* __restrict__ rd) {
    int r = blockIdx.x * blockDim.x + threadIdx.x;
    if (r >= NR) return;
    const float* zb = flag ? g_z1 : g_z0;
    const float* fb = flag ? g_s1 : g_s0;
    float ox = ro[3 * r], oy = ro[3 * r + 1], oz = ro[3 * r + 2];
    float dx = rd[3 * r], dy = rd[3 * r + 1], dz = rd[3 * r + 2];

    float T = 1.f, wsum = 0.f, cprev = 0.f;
    float z0v = zb[r], f0 = fb[r];
    float px = ox + dx * z0v, py = oy + dy * z0v, pz = oz + dz * z0v;
    float rad_prev = sqrtf(px * px + py * py + pz * pz);
    for (int k = 0; k < S - 1; k++) {
        float z1v = zb[(k + 1) * NR + r], f1 = fb[(k + 1) * NR + r];
        float qx = ox + dx * z1v, qy = oy + dy * z1v, qz = oz + dz * z1v;
        float rad_next = sqrtf(qx * qx + qy * qy + qz * qz);
        float inside = (rad_prev < 1.f || rad_next < 1.f) ? 1.f : 0.f;
        rad_prev = rad_next;
        float c = (f1 - f0) / (z1v - z0v + 1e-5f);
        float cc = fminf((k == 0) ? 0.f : cprev, c);
        cprev = c;
        cc = fminf(fmaxf(cc, -1000.f), 0.f) * inside;
        float midv = 0.5f * (f0 + f1);
        float dd = z1v - z0v;
        float pc = sigmoidf((midv - cc * dd * 0.5f) * inv_s);
        float nc = sigmoidf((midv + cc * dd * 0.5f) * inv_s);
        float a = (pc - nc + 1e-5f) / (pc + 1e-5f);
        float wk = a * T + 1e-5f;
        T *= (1.f - a + 1e-7f);
        g_w[k * NR + r] = wk;
        wsum += wk;
        z0v = z1v; f0 = f1;
    }

    int t = 0;
    float cb = 0.f, run = 0.f;
    z0v = zb[r];
    for (int k = 0; k < S - 1 && t < 16; k++) {
        float z1v = zb[(k + 1) * NR + r];
        run += g_w[k * NR + r] / wsum;
        while (t < 16) {
            float u = (float)(2 * t + 1) * 0.03125f;
            if (!(u < run)) break;
            float denom = run - cb;
            if (denom < 1e-5f) denom = 1.f;
            float tt = (u - cb) / denom;
            g_newz[t * NR + r] = z0v + tt * (z1v - z0v);
            t++;
        }
        cb = run; z0v = z1v;
    }
    float zlast = zb[(S - 1) * NR + r];
    while (t < 16) { g_newz[t * NR + r] = zlast; t++; }
}

// ---------------- per-ray stable merge (streaming, ping-pong) ----------------
__global__ void k_merge(int S, int flag, int last) {
    int r = blockIdx.x * blockDim.x + threadIdx.x;
    if (r >= NR) return;
    const float* zi = flag ? g_z1 : g_z0;
    float* zo = flag ? g_z0 : g_z1;
    const float* si = flag ? g_s1 : g_s0;
    float* so = flag ? g_s0 : g_s1;
    int i = 0, j = 0;
    float zv = zi[r], nv = g_newz[r];
    for (int t = 0; t < S + 16; t++) {
        bool takeold = (j >= 16) || (i < S && zv <= nv);
        if (takeold) {
            zo[t * NR + r] = zv;
            if (!last) so[t * NR + r] = si[i * NR + r];
            i++;
            if (i < S) zv = zi[i * NR + r];
        } else {
            zo[t * NR + r] = nv;
            if (!last) so[t * NR + r] = g_newsdf[j * NR + r];
            j++;
            if (j < 16) nv = g_newz[j * NR + r];
        }
    }
}

// ---------------- per-ray render (depth) ----------------
__global__ void k_render(const float* __restrict__ variance, float* __restrict__ out) {
    int r = blockIdx.x * blockDim.x + threadIdx.x;
    if (r >= NR) return;
    float inv_s = expf(10.f * variance[0]);
    inv_s = fminf(fmaxf(inv_s, 1e-6f), 1e6f);
    float T = 1.f, depth = 0.f;
    for (int k = 0; k < 128; k++) {
        float zk = g_z0[k * NR + r];
        float dist = (k < 127) ? (g_z0[(k + 1) * NR + r] - zk) : 0.03125f;
        float tc = g_tc[k * NR + r];
        float itc = -fmaxf(0.5f - 0.5f * tc, 0.f);   // COS_ANNEAL_RATIO = 0
        float sdf = g_fsdf[k * NR + r];
        float pc = sigmoidf((sdf - itc * dist * 0.5f) * inv_s);
        float nc = sigmoidf((sdf + itc * dist * 0.5f) * inv_s);
        float a = (pc - nc + 1e-5f) / (pc + 1e-5f);
        a = fminf(fmaxf(a, 0.f), 1.f);
        depth += a * T * zk;
        T *= (1.f - a + 1e-7f);
    }
    out[r] = depth;
}

// ---------------- launch ----------------
extern "C" void kernel_launch(void* const* d_in, const int* in_sizes, int n_in,
                              void* d_out, int out_size) {
    const float* rays_o = (const float*)d_in[0];
    const float* rays_d = (const float*)d_in[1];
    const float* near_  = (const float*)d_in[2];
    const float* far_   = (const float*)d_in[3];
    const float* W1 = (const float*)d_in[4];
    const float* b1 = (const float*)d_in[5];
    const float* W2 = (const float*)d_in[6];
    const float* b2 = (const float*)d_in[7];
    const float* W3 = (const float*)d_in[8];
    const float* b3 = (const float*)d_in[9];
    const float* var = (const float*)d_in[10];
    float* out = (float*)d_out;

    cudaFuncSetAttribute(k_mlp_fwd,    cudaFuncAttributeMaxDynamicSharedMemorySize, SMEM_F);
    cudaFuncSetAttribute(k_mlp_fwd_g2, cudaFuncAttributeMaxDynamicSharedMemorySize, SMEM_F);
    cudaFuncSetAttribute(k_mlp_bwd,    cudaFuncAttributeMaxDynamicSharedMemorySize, SMEM_BWD);

    // initial coarse sampling: S=64 (262144 points -> 2048 tiles)
    k_init_z<<<(NR * 64) / 256, 256>>>(near_, far_);
    k_mlp_fwd<<<(NR * 64) / 128, 256, SMEM_F>>>(W1, b1, W2, b2, W3, b3, rays_o, rays_d, 0);

    // 4 upsample rounds, +16 samples each; z/sdf ping-pong
    for (int i = 0; i < 4; i++) {
        int S = 64 + 16 * i;
        float inv_s = (float)(64 << i);
        int flag = i & 1;
        k_upsample<<<NR / 32, 32>>>(S, inv_s, flag, rays_o, rays_d);
        if (i < 3)
            k_mlp_fwd<<<(NR * 16) / 128, 256, SMEM_F>>>(W1, b1, W2, b2, W3, b3, rays_o, rays_d, 1);
        k_merge<<<NR / 32, 32>>>(S, flag, (i == 3) ? 1 : 0);
    }

    // final: S=128 (524288 points -> 4096 tiles): fwd(+g2), bwd, render
    k_mlp_fwd_g2<<<(NR * 128) / 128, 256, SMEM_F>>>(W1, b1, W2, b2, W3, b3, rays_o, rays_d);
    k_mlp_bwd<<<(NR * 128) / 128, 256, SMEM_BWD>>>(W1, b1, W2, rays_o, rays_d, out + NR);
    k_render<<<NR / 32, 32>>>(var, out);
}